// round 6
// baseline (speedup 1.0000x reference)
#include <cuda_runtime.h>
#include <cuda_bf16.h>

#define DIM 128

// One block (128 threads) per batch element.
// score[b] = - sum_{m,k} hhat[m] * R[m*128+k] * that[k]
// Threads read R flat & coalesced: per iteration group of 4 rows, thread k
// loads float4 at row (m0 + (k>>5)), cols 4*(k&31)..+3.
__global__ __launch_bounds__(128, 8) void rescal_kernel(
    const int*   __restrict__ sample,      // [BATCH, 3] int32 (JAX default x64-off)
    const float* __restrict__ ent,         // [N_ENT, 128]
    const float* __restrict__ rel,         // [N_REL, 128*128]
    float*       __restrict__ out)         // [BATCH]
{
    __shared__ float h_s[DIM];
    __shared__ __align__(16) float t_s[DIM];
    __shared__ float red[8];

    const int b    = blockIdx.x;
    const int k    = threadIdx.x;
    const int lane = k & 31;
    const int warp = k >> 5;

    const int hi = sample[3 * b + 0];
    const int ri = sample[3 * b + 1];
    const int ti = sample[3 * b + 2];

    const float eh = ent[(size_t)hi * DIM + k];
    const float et = ent[(size_t)ti * DIM + k];

    // --- L2 norms of the two gathered embeddings (block reduction) ---
    float sh = eh * eh;
    float st = et * et;
    #pragma unroll
    for (int o = 16; o > 0; o >>= 1) {
        sh += __shfl_xor_sync(0xffffffffu, sh, o);
        st += __shfl_xor_sync(0xffffffffu, st, o);
    }
    if (lane == 0) { red[warp] = sh; red[4 + warp] = st; }
    __syncthreads();
    const float nh = fmaxf(sqrtf(red[0] + red[1] + red[2] + red[3]), 1e-12f);
    const float nt = fmaxf(sqrtf(red[4] + red[5] + red[6] + red[7]), 1e-12f);

    h_s[k] = eh / nh;
    t_s[k] = et / nt;
    __syncthreads();

    // Per-thread fixed column group and row offset within each 4-row sweep.
    const int cg = lane;        // 0..31  -> columns 4*cg .. 4*cg+3
    const int ro = warp;        // 0..3   -> row m0 + ro

    const float4 t4 = reinterpret_cast<const float4*>(t_s)[cg];

    const float4* __restrict__ R4 =
        reinterpret_cast<const float4*>(rel + (size_t)ri * (DIM * DIM));

    float acc = 0.0f;
    #pragma unroll 8
    for (int m0 = 0; m0 < DIM; m0 += 4) {
        const int row = m0 + ro;
        const float4 Rv = R4[row * 32 + cg];
        const float hm  = h_s[row];
        float d = Rv.x * t4.x;
        d = fmaf(Rv.y, t4.y, d);
        d = fmaf(Rv.z, t4.z, d);
        d = fmaf(Rv.w, t4.w, d);
        acc = fmaf(hm, d, acc);
    }

    // --- block reduce acc over 128 threads ---
    #pragma unroll
    for (int o = 16; o > 0; o >>= 1)
        acc += __shfl_xor_sync(0xffffffffu, acc, o);
    __syncthreads();            // red[] reuse
    if (lane == 0) red[warp] = acc;
    __syncthreads();
    if (k == 0)
        out[b] = -(red[0] + red[1] + red[2] + red[3]);
}

extern "C" void kernel_launch(void* const* d_in, const int* in_sizes, int n_in,
                              void* d_out, int out_size)
{
    const int*   sample = (const int*)d_in[0];
    const float* ent    = (const float*)d_in[1];
    const float* rel    = (const float*)d_in[2];
    float*       out    = (float*)d_out;

    const int batch = in_sizes[0] / 3;   // sample has BATCH*3 elements
    rescal_kernel<<<batch, 128>>>(sample, ent, rel, out);
}